// round 14
// baseline (speedup 1.0000x reference)
#include <cuda_runtime.h>
#include <cuda_fp16.h>
#include <math.h>

#define NB 128
#define NT 512
#define Bsz 128
#define Ssz 512
#define Dsz 128
#define Hsz 1024
#define Gsz 4096
#define KENC 1152
#define KDEC 1024
#define NCENC 9            // 9 x 128-k chunks (chunk0 = x_t)
#define NCDEC 8
#define WSTR 1160          // smem W row stride (halfs)
#define ASTR 136           // smem A row stride (halfs)
#define OSTR 66            // smem O row stride (floats)
#define WBYTES (64*WSTR*2)                  // 148480
#define ABYTES (64*ASTR*2)                  // 17408
#define CSOFF  (WBYTES + 4*ABYTES)          // Csm (4KB)
#define BSOFF  (CSOFF + 4096)               // Bsm (256B)
#define SMEM_BYTES (BSOFF + 256)            // 222464 (< 227KB cap)

#define RECONSZ (Bsz*Ssz*Dsz)      /* 8388608  */
#define ENCSZ   (Bsz*Ssz*Hsz)      /* 67108864 */
#define ENCOFF  RECONSZ
#define TOTSZ   (RECONSZ+ENCSZ+1)  /* 75497473 */

// ---------------- device scratch (static: no allocations) ----------------
__device__ __align__(16) __half  g_Xh[(size_t)Bsz*Ssz*Dsz];     // 16 MB
__device__ __align__(16) __half  g_Hbuf[2][(size_t)Bsz*Hsz];    // double-buffered h
__device__ __align__(16) __half  g_Hdec[(size_t)Bsz*Ssz*Hsz];   // 128 MB decoder h's
__device__ __align__(16) __half  g_Wcomb[(size_t)Gsz*Hsz];      // Whh + Wih[:,:128]@out_W
__device__ __align__(16) __half  g_oWh[(size_t)Dsz*Hsz];        // out_W in fp16
__device__ float  g_Benc[Gsz];
__device__ float  g_Bdec0[Gsz];
__device__ float  g_BdecC[Gsz];
__device__ double g_loss;
// init barrier (full grid, used once): monotonic counters
__device__ unsigned g_grpcnt[8];
__device__ unsigned g_rootcnt;
__device__ volatile unsigned g_gen;
// dataflow counters: [rg][h-chunk], padded to 128B lines, monotonic (+8 per step).
// NEVER reset; all waits use a per-launch base captured BEFORE the init barrier,
// which is provably the launch-entry value (no increment can precede the barrier).
__device__ unsigned g_chk[2][8 * 32];

// ---------------- full-grid barrier (init only) ----------------
__device__ __forceinline__ void grid_sync_all() {
    __syncthreads();
    if (threadIdx.x == 0) {
        unsigned g = g_gen;
        __threadfence();
        unsigned a = atomicAdd(&g_grpcnt[blockIdx.x >> 4], 1u);
        if ((a & 15u) == 15u) {
            unsigned r = atomicAdd(&g_rootcnt, 1u);
            if ((r & 7u) == 7u) { __threadfence(); g_gen = g + 1u; }
        }
        while (g_gen == g) { __nanosleep(20); }
        __threadfence();
    }
    __syncthreads();
}

// tid0-only: wait until h-chunk hc of row-group rg reaches target level
__device__ __forceinline__ void wait_ready(int rg, int hc, unsigned tgt) {
    volatile unsigned* p = &g_chk[rg][hc * 32];
    while ((int)(*p - tgt) < 0) { __nanosleep(20); }   // wrap-safe compare
    __threadfence();   // acquire: order subsequent loads after observation
}

__device__ __forceinline__ float sigf(float x) { return 1.f / (1.f + __expf(-x)); }

// ---------------- A-tile loader: 64 rows x 128 k-halfs via cp.async ----------------
// MODE 0: encoder (chunk 0 = x_t, chunks 1.. = h), MODE 1: decoder (all h)
template<int MODE>
__device__ __forceinline__ void loadA(__half* As, int c, int rowbase, int t,
                                      int tid, const __half* __restrict__ hin) {
#pragma unroll
    for (int i = 0; i < 2; i++) {
        int idx = tid + i * NT;          // 0..1023 -> 1024 x 16B segments
        int r   = idx >> 4;
        int kq  = (idx & 15) * 8;
        const __half* gp;
        if (MODE == 0 && c == 0) {
            gp = g_Xh + ((size_t)(rowbase + r) * Ssz + t) * Dsz + kq;
        } else {
            int kc = (MODE == 0) ? (c - 1) * 128 : c * 128;
            gp = hin + (size_t)(rowbase + r) * Hsz + kc + kq;
        }
        unsigned sa = (unsigned)__cvta_generic_to_shared(As + r * ASTR + kq);
        asm volatile("cp.async.cg.shared.global [%0], [%1], 16;\n" :: "r"(sa), "l"(gp));
    }
    asm volatile("cp.async.commit_group;\n" ::: "memory");
}

// ---------------- 64x64 tile GEMM with per-chunk dataflow waits ----------------
// 16 warps, 4x4 grid, warp tile 16x16. 4 A buffers, lookahead 2.
template<int NC, int MODE>
__device__ __forceinline__ void gemm_step(const __half* __restrict__ Ws,
                                          __half* Ab, float* Osm,
                                          int rowbase, int t,
                                          const __half* __restrict__ hin,
                                          bool pre0, int rg, unsigned tgt) {
    const int tid  = threadIdx.x;
    const int wid  = tid >> 5, lane = tid & 31;
    const int wr   = wid >> 2, wc   = wid & 3;
    const int quad = lane >> 2, tq  = lane & 3;

    const int aRow = lane & 15;
    const int aK   = ((lane >> 4) & 1) * 8;
    const int bN   = ((lane >> 4) * 8) + (lane & 7);
    const int bK   = ((lane >> 3) & 1) * 8;

    float acc[2][4];
#pragma unroll
    for (int ni = 0; ni < 2; ni++)
#pragma unroll
        for (int q = 0; q < 4; q++) acc[ni][q] = 0.f;

    // prologue: ensure chunks 0,1 ready; issue their loads
    if (tid == 0) {
        if (MODE == 1 && !pre0) wait_ready(rg, 0, tgt);
        wait_ready(rg, (MODE == 0) ? 0 : 1, tgt);   // chunk1's h-chunk
    }
    __syncthreads();
    if (!pre0) loadA<MODE>(Ab, 0, rowbase, t, tid, hin);
    loadA<MODE>(Ab + 64 * ASTR, 1, rowbase, t, tid, hin);

    for (int c = 0; c < NC; c++) {
        if (tid == 0 && c + 2 < NC)
            wait_ready(rg, (MODE == 0) ? (c + 1) : (c + 2), tgt);
        if (c + 1 < NC) asm volatile("cp.async.wait_group 1;\n" ::: "memory");
        else            asm volatile("cp.async.wait_group 0;\n" ::: "memory");
        __syncthreads();    // buffer c landed; all warps done with buffer (c-2); flag broadcast
        if (c + 2 < NC)
            loadA<MODE>(Ab + ((c + 2) & 3) * 64 * ASTR, c + 2, rowbase, t, tid, hin);

        const __half* cur   = Ab + (c & 3) * 64 * ASTR;
        const __half* bbase = Ws + (size_t)(wc * 16 + bN) * WSTR + c * 128 + bK;
        const __half* abase = cur + (wr * 16 + aRow) * ASTR + aK;

        unsigned bfr[8][4];
#pragma unroll
        for (int kk = 0; kk < 8; kk++) {
            unsigned ba = (unsigned)__cvta_generic_to_shared(bbase + kk * 16);
            asm volatile(
                "ldmatrix.sync.aligned.m8n8.x4.shared.b16 {%0,%1,%2,%3}, [%4];\n"
                : "=r"(bfr[kk][0]), "=r"(bfr[kk][1]), "=r"(bfr[kk][2]), "=r"(bfr[kk][3])
                : "r"(ba));
        }
#pragma unroll
        for (int kk = 0; kk < 8; kk++) {
            unsigned a0, a1, a2, a3;
            unsigned aa = (unsigned)__cvta_generic_to_shared(abase + kk * 16);
            asm volatile(
                "ldmatrix.sync.aligned.m8n8.x4.shared.b16 {%0,%1,%2,%3}, [%4];\n"
                : "=r"(a0), "=r"(a1), "=r"(a2), "=r"(a3) : "r"(aa));
            asm volatile(
                "mma.sync.aligned.m16n8k16.row.col.f32.f16.f16.f32 "
                "{%0,%1,%2,%3}, {%4,%5,%6,%7}, {%8,%9}, {%0,%1,%2,%3};\n"
                : "+f"(acc[0][0]), "+f"(acc[0][1]), "+f"(acc[0][2]), "+f"(acc[0][3])
                : "r"(a0), "r"(a1), "r"(a2), "r"(a3), "r"(bfr[kk][0]), "r"(bfr[kk][1]));
            asm volatile(
                "mma.sync.aligned.m16n8k16.row.col.f32.f16.f16.f32 "
                "{%0,%1,%2,%3}, {%4,%5,%6,%7}, {%8,%9}, {%0,%1,%2,%3};\n"
                : "+f"(acc[1][0]), "+f"(acc[1][1]), "+f"(acc[1][2]), "+f"(acc[1][3])
                : "r"(a0), "r"(a1), "r"(a2), "r"(a3), "r"(bfr[kk][2]), "r"(bfr[kk][3]));
        }
    }
    __syncthreads();   // all compute done before Osm (A-buffer alias) is written
#pragma unroll
    for (int ni = 0; ni < 2; ni++) {
        int row = wr * 16 + quad;
        int col = wc * 16 + ni * 8 + tq * 2;
        *(float2*)&Osm[row * OSTR + col]       = make_float2(acc[ni][0], acc[ni][1]);
        *(float2*)&Osm[(row + 8) * OSTR + col] = make_float2(acc[ni][2], acc[ni][3]);
    }
    __syncthreads();   // Osm complete before pointwise reads / prefetch into buf0
}

// ---------------- LSTM pointwise: 512 threads, 1 half2 each ----------------
__device__ __forceinline__ void pointwise(const float* __restrict__ Osm,
                                          const float* __restrict__ Bsm,
                                          float* __restrict__ Csm,
                                          int rg, int cg, int t,
                                          float* __restrict__ out,
                                          __half* __restrict__ hout,
                                          int writeEnc, int writeDec) {
    const int tid = threadIdx.x;
    int row = tid >> 3;            // 0..63
    int jc  = (tid & 7) * 2;       // 0,2..14
    int hc  = cg * 16 + jc;
    int bg  = rg * 64 + row;
    float2 i2 = *(const float2*)&Osm[row * OSTR + jc];
    float2 f2 = *(const float2*)&Osm[row * OSTR + 16 + jc];
    float2 g2 = *(const float2*)&Osm[row * OSTR + 32 + jc];
    float2 o2 = *(const float2*)&Osm[row * OSTR + 48 + jc];
    float iv0 = sigf(i2.x + Bsm[jc]),       iv1 = sigf(i2.y + Bsm[jc + 1]);
    float fv0 = sigf(f2.x + Bsm[16 + jc]),  fv1 = sigf(f2.y + Bsm[17 + jc]);
    float gv0 = tanhf(g2.x + Bsm[32 + jc]), gv1 = tanhf(g2.y + Bsm[33 + jc]);
    float ov0 = sigf(o2.x + Bsm[48 + jc]),  ov1 = sigf(o2.y + Bsm[49 + jc]);
    float2 cold = *(const float2*)&Csm[row * 16 + jc];
    float c0 = fv0 * cold.x + iv0 * gv0;
    float c1 = fv1 * cold.y + iv1 * gv1;
    *(float2*)&Csm[row * 16 + jc] = make_float2(c0, c1);
    float h0 = ov0 * tanhf(c0), h1 = ov1 * tanhf(c1);
    size_t off = (size_t)bg * Hsz + hc;
    *(__half2*)&hout[off] = __floats2half2_rn(h0, h1);
    if (writeEnc)
        *(float2*)&out[(size_t)ENCOFF + ((size_t)bg * Ssz + t) * Hsz + hc] = make_float2(h0, h1);
    if (writeDec)
        *(__half2*)&g_Hdec[((size_t)bg * Ssz + t) * Hsz + hc] = __floats2half2_rn(h0, h1);
}

// ============================== persistent LSTM kernel ==============================
__global__ void __launch_bounds__(NT, 1)
lstm_ae_kernel(const float* __restrict__ x,
               const float* __restrict__ eWih, const float* __restrict__ eWhh,
               const float* __restrict__ ebih, const float* __restrict__ ebhh,
               const float* __restrict__ dWih, const float* __restrict__ dWhh,
               const float* __restrict__ dbih, const float* __restrict__ dbhh,
               const float* __restrict__ oW,   const float* __restrict__ ob,
               float* __restrict__ out, int out_size) {
    extern __shared__ __align__(16) char smem_raw[];
    __half* Ws  = (__half*)smem_raw;
    __half* Ab  = (__half*)(smem_raw + WBYTES);             // 4 A buffers
    float*  Osm = (float*)(smem_raw + WBYTES + ABYTES);     // aliases buf1
    float*  Csm = (float*)(smem_raw + CSOFF);               // cell state (CTA-private)
    float*  Bsm = (float*)(smem_raw + BSOFF);               // 64 bias floats

    const int bid = blockIdx.x, tid = threadIdx.x;
    const int rg = bid >> 6;      // batch-row group (0..1)
    const int cg = bid & 63;      // h-col group (0..63)
    const int myChunk = cg >> 3;  // which h-chunk this CTA produces
    const int hasEnc = (out_size >= RECONSZ + ENCSZ) ? 1 : 0;

    // Per-launch counter base. Read BEFORE grid_sync_all: no increment in this
    // launch can precede the barrier (every CTA, incl. this one, must arrive
    // first), so this is exactly the launch-entry value — replay-safe.
    const unsigned cbase = *((volatile unsigned*)&g_chk[rg][0]);

    // ================= init =================
    if (bid == 0 && tid == 0) g_loss = 0.0;

    {   // x -> fp16
        const float4* xv = (const float4*)x;
        __half2* hp = (__half2*)g_Xh;
        size_t n4 = (size_t)Bsz * Ssz * Dsz / 4;
        for (size_t i = (size_t)bid * NT + tid; i < n4; i += (size_t)NB * NT) {
            float4 v = xv[i];
            hp[i * 2]     = __floats2half2_rn(v.x, v.y);
            hp[i * 2 + 1] = __floats2half2_rn(v.z, v.w);
        }
    }
    for (int i = bid * NT + tid; i < Bsz * Hsz; i += NB * NT)
        g_Hbuf[0][i] = __float2half(0.f);
    for (int i = bid * NT + tid; i < Dsz * Hsz; i += NB * NT)
        g_oWh[i] = __float2half(oW[i]);
    for (int R = bid * NT + tid; R < Gsz; R += NB * NT) {
        g_Benc[R] = ebih[R] + ebhh[R];
        float b0 = dbih[R] + dbhh[R];
        g_Bdec0[R] = b0;
        float s = 0.f;
        const float* wr_ = dWih + (size_t)R * Hsz;
        for (int d = 0; d < 128; d++) s += wr_[d] * ob[d];
        g_BdecC[R] = b0 + s;
    }
    {   // Wcomb = dec_Whh + dec_Wih[:,:128] @ out_W   (this block: rows bid*32..+32)
        int R0 = bid * 32;
        int qr = tid >> 7;                  // 0..3 -> 8-row slices
        int k0 = (tid & 127) * 8;
        for (int r = qr * 8; r < qr * 8 + 8; r++) {
            int R = R0 + r;
            const float* wr_ = dWih + (size_t)R * Hsz;
            float a8[8];
#pragma unroll
            for (int q = 0; q < 8; q++) a8[q] = dWhh[(size_t)R * Hsz + k0 + q];
            for (int d = 0; d < 128; d++) {
                float w = wr_[d];
                const float* owp = oW + (size_t)d * Hsz + k0;
#pragma unroll
                for (int q = 0; q < 8; q++) a8[q] += w * owp[q];
            }
#pragma unroll
            for (int q = 0; q < 8; q++)
                g_Wcomb[(size_t)R * Hsz + k0 + q] = __float2half(a8[q]);
        }
    }
    grid_sync_all();

    int par = 0;   // h read-buffer parity

    // ================= encoder =================
    loadA<0>(Ab, 0, rg * 64, 0, tid, (const __half*)0);   // prefetch x(t=0)

    for (int i = tid; i < 1024; i += NT) Csm[i] = 0.f;
    if (tid < 64) Bsm[tid] = g_Benc[(tid >> 4) * Hsz + cg * 16 + (tid & 15)];
    for (int r = 0; r < 64; r++) {
        int R = (r >> 4) * Hsz + cg * 16 + (r & 15);
        for (int k = tid; k < KENC; k += NT) {
            float v = (k < 128) ? eWih[(size_t)R * Dsz + k] : eWhh[(size_t)R * Hsz + (k - 128)];
            Ws[r * WSTR + k] = __float2half(v);
        }
    }
    __syncthreads();
    for (int t = 0; t < Ssz; t++) {
        gemm_step<NCENC, 0>(Ws, Ab, Osm, rg * 64, t, g_Hbuf[par], true, rg,
                            cbase + 8u * (unsigned)t);
        if (t + 1 < Ssz)
            loadA<0>(Ab, 0, rg * 64, t + 1, tid, (const __half*)0);   // x prefetch (always ready)
        pointwise(Osm, Bsm, Csm, rg, cg, t, out, g_Hbuf[par ^ 1], hasEnc, 0);
        par ^= 1;
        __syncthreads();   // all h writes done before release
        if (tid == 0) { __threadfence(); atomicAdd(&g_chk[rg][myChunk * 32], 1u); }
    }

    // ================= decoder step 0 (input = h_n, weights Wih+Whh) =================
    if (tid < 64) Bsm[tid] = g_Bdec0[(tid >> 4) * Hsz + cg * 16 + (tid & 15)];
    for (int r = 0; r < 64; r++) {
        int R = (r >> 4) * Hsz + cg * 16 + (r & 15);
        for (int k = tid; k < KDEC; k += NT)
            Ws[r * WSTR + k] = __float2half(dWih[(size_t)R * Hsz + k] + dWhh[(size_t)R * Hsz + k]);
    }
    __syncthreads();
    gemm_step<NCDEC, 1>(Ws, Ab, Osm, rg * 64, 0, g_Hbuf[par], false, rg, cbase + 8u * 512u);
    pointwise(Osm, Bsm, Csm, rg, cg, 0, out, g_Hbuf[par ^ 1], 0, 1);
    par ^= 1;
    __syncthreads();
    if (tid == 0) { __threadfence(); atomicAdd(&g_chk[rg][myChunk * 32], 1u); }

    // ================= decoder steps 1..511 (folded weights) =================
    if (tid < 64) Bsm[tid] = g_BdecC[(tid >> 4) * Hsz + cg * 16 + (tid & 15)];
    for (int s = tid; s < 64 * 128; s += NT) {     // 8192 x uint4 segments
        int r  = s >> 7;
        int sg = (s & 127) * 8;
        int R  = (r >> 4) * Hsz + cg * 16 + (r & 15);
        *(uint4*)&Ws[r * WSTR + sg] = *(const uint4*)&g_Wcomb[(size_t)R * Hsz + sg];
    }
    __syncthreads();
    for (int t = 1; t < Ssz; t++) {
        gemm_step<NCDEC, 1>(Ws, Ab, Osm, rg * 64, t, g_Hbuf[par], false, rg,
                            cbase + 8u * (unsigned)(512 + t));
        pointwise(Osm, Bsm, Csm, rg, cg, t, out, g_Hbuf[par ^ 1], 0, 1);
        par ^= 1;
        __syncthreads();
        if (tid == 0) { __threadfence(); atomicAdd(&g_chk[rg][myChunk * 32], 1u); }
    }
}

// ============== recon = Hdec @ out_W^T + out_b  (+ fused loss) ==============
__global__ void __launch_bounds__(256)
recon_kernel(const float* __restrict__ x, const float* __restrict__ ob,
             float* __restrict__ out, int out_size) {
    __shared__ __align__(16) __half Asm[64 * ASTR];
    __shared__ __align__(16) __half Wsm[128 * ASTR];

    const int tid  = threadIdx.x;
    const int wid  = tid >> 5, lane = tid & 31;
    const int wr   = wid >> 2, wc   = wid & 3;     // 2x4 warps -> 64x128 tile
    const int quad = lane >> 2, tq  = lane & 3;
    const int rowbase = blockIdx.x * 64;           // 1024 blocks
    const int doRecon = (out_size >= RECONSZ) ? 1 : 0;

    float acc[2][4][4];
#pragma unroll
    for (int mi = 0; mi < 2; mi++)
#pragma unroll
        for (int ni = 0; ni < 4; ni++)
#pragma unroll
            for (int q = 0; q < 4; q++) acc[mi][ni][q] = 0.f;

    for (int c = 0; c < 16; c++) {
        const int kabs = c * 64;
#pragma unroll
        for (int j = 0; j < 2; j++) {   // A: 64 rows x 64 halfs
            int idx = tid + j * 256;
            int r = idx >> 3, kq = (idx & 7) * 8;
            *(uint4*)&Asm[r * ASTR + kq] =
                *(const uint4*)(g_Hdec + (size_t)(rowbase + r) * Hsz + kabs + kq);
        }
#pragma unroll
        for (int j = 0; j < 4; j++) {   // W: 128 rows x 64 halfs
            int idx = tid + j * 256;
            int n = idx >> 3, kq = (idx & 7) * 8;
            *(uint4*)&Wsm[n * ASTR + kq] =
                *(const uint4*)(g_oWh + (size_t)n * Hsz + kabs + kq);
        }
        __syncthreads();
#pragma unroll
        for (int kk = 0; kk < 4; kk++) {
            unsigned bfr[4][2];
#pragma unroll
            for (int ni = 0; ni < 4; ni++) {
                const __half* bp = Wsm + (wc * 32 + ni * 8 + quad) * ASTR + kk * 16 + tq * 2;
                bfr[ni][0] = *(const unsigned*)bp;
                bfr[ni][1] = *(const unsigned*)(bp + 8);
            }
#pragma unroll
            for (int mi = 0; mi < 2; mi++) {
                const __half* ap = Asm + (wr * 32 + mi * 16 + quad) * ASTR + kk * 16 + tq * 2;
                unsigned a0 = *(const unsigned*)ap;
                unsigned a1 = *(const unsigned*)(ap + 8 * ASTR);
                unsigned a2 = *(const unsigned*)(ap + 8);
                unsigned a3 = *(const unsigned*)(ap + 8 * ASTR + 8);
#pragma unroll
                for (int ni = 0; ni < 4; ni++)
                    asm volatile(
                        "mma.sync.aligned.m16n8k16.row.col.f32.f16.f16.f32 "
                        "{%0,%1,%2,%3}, {%4,%5,%6,%7}, {%8,%9}, {%0,%1,%2,%3};\n"
                        : "+f"(acc[mi][ni][0]), "+f"(acc[mi][ni][1]),
                          "+f"(acc[mi][ni][2]), "+f"(acc[mi][ni][3])
                        : "r"(a0), "r"(a1), "r"(a2), "r"(a3),
                          "r"(bfr[ni][0]), "r"(bfr[ni][1]));
            }
        }
        __syncthreads();
    }

    // epilogue: add bias, write recon, accumulate loss
    float lsum = 0.f;
#pragma unroll
    for (int mi = 0; mi < 2; mi++)
#pragma unroll
        for (int ni = 0; ni < 4; ni++) {
            int row = rowbase + wr * 32 + mi * 16 + quad;
            int col = wc * 32 + ni * 8 + tq * 2;
            float b0 = ob[col], b1 = ob[col + 1];
#pragma unroll
            for (int half_ = 0; half_ < 2; half_++) {
                int rr = row + half_ * 8;
                float v0 = acc[mi][ni][half_ * 2]     + b0;
                float v1 = acc[mi][ni][half_ * 2 + 1] + b1;
                size_t o = (size_t)rr * Dsz + col;
                float d0 = v0 - x[o], d1 = v1 - x[o + 1];
                lsum += d0 * d0 + d1 * d1;
                if (doRecon) { out[o] = v0; out[o + 1] = v1; }
            }
        }
#pragma unroll
    for (int off = 16; off > 0; off >>= 1)
        lsum += __shfl_xor_sync(0xffffffffu, lsum, off);
    if (lane == 0) atomicAdd(&g_loss, (double)lsum);
}

__global__ void loss_finish(float* __restrict__ out, int out_size) {
    if (out_size >= TOTSZ) out[RECONSZ + ENCSZ] = (float)(g_loss * (1.0 / 128.0));
}

// ============================== launch ==============================
extern "C" void kernel_launch(void* const* d_in, const int* in_sizes, int n_in,
                              void* d_out, int out_size) {
    const float* x     = (const float*)d_in[0];
    const float* eWih  = (const float*)d_in[1];
    const float* eWhh  = (const float*)d_in[2];
    const float* ebih  = (const float*)d_in[3];
    const float* ebhh  = (const float*)d_in[4];
    const float* dWih  = (const float*)d_in[5];
    const float* dWhh  = (const float*)d_in[6];
    const float* dbih  = (const float*)d_in[7];
    const float* dbhh  = (const float*)d_in[8];
    const float* oW    = (const float*)d_in[9];
    const float* ob    = (const float*)d_in[10];
    float* out = (float*)d_out;

    cudaFuncSetAttribute(lstm_ae_kernel,
                         cudaFuncAttributeMaxDynamicSharedMemorySize, SMEM_BYTES);

    lstm_ae_kernel<<<NB, NT, SMEM_BYTES>>>(x, eWih, eWhh, ebih, ebhh,
                                           dWih, dWhh, dbih, dbhh, oW, ob,
                                           out, out_size);
    recon_kernel<<<(Bsz * Ssz) / 64, 256>>>(x, ob, out, out_size);
    loss_finish<<<1, 1>>>(out, out_size);
}

// round 15
// speedup vs baseline: 1.5165x; 1.5165x over previous
#include <cuda_runtime.h>
#include <cuda_fp16.h>
#include <math.h>

#define NB 128
#define NT 512
#define Bsz 128
#define Ssz 512
#define Dsz 128
#define Hsz 1024
#define Gsz 4096
#define NCENC 18           // 18 x 64-k chunks (chunks 0,1 = x_t)
#define NCDEC 16
#define WSTR 1160          // smem W row stride (halfs); 2320B
#define ASTR 72            // A chunk row stride (halfs); 144B
#define OSTR 66            // Osm row stride (floats)
#define RSTR 34            // reduction tile row stride (floats)
#define WBYTES (64*WSTR*2)                  // 148480
#define ABUF   (64*ASTR*2)                  // 9216 per buffer
#define AOFF   WBYTES                       // 8 buffers: 73728
#define REDOFF AOFF                         // overlay: 12 x 32*34 floats = 52224
#define OSMOFF (AOFF + 52224)               // 16896 -> ends 69120 <= 73728
#define CSOFF  (AOFF + 8*ABUF)              // 222208: Csm 4KB
#define BSOFF  (CSOFF + 4096)               // 226304: Bsm 256B
#define SMEM_BYTES (BSOFF + 256)            // 226560 < 232448 cap

#define RECONSZ (Bsz*Ssz*Dsz)      /* 8388608  */
#define ENCSZ   (Bsz*Ssz*Hsz)      /* 67108864 */
#define ENCOFF  RECONSZ
#define TOTSZ   (RECONSZ+ENCSZ+1)  /* 75497473 */

// ---------------- device scratch (static: no allocations) ----------------
__device__ __align__(16) __half  g_Xh[(size_t)Bsz*Ssz*Dsz];     // 16 MB
__device__ __align__(16) __half  g_Hbuf[2][(size_t)Bsz*Hsz];    // double-buffered h
__device__ __align__(16) __half  g_Hdec[(size_t)Bsz*Ssz*Hsz];   // 128 MB decoder h's
__device__ __align__(16) __half  g_Wcomb[(size_t)Gsz*Hsz];      // Whh + Wih[:,:128]@out_W
__device__ __align__(16) __half  g_oWh[(size_t)Dsz*Hsz];        // out_W in fp16
__device__ float  g_Benc[Gsz];
__device__ float  g_Bdec0[Gsz];
__device__ float  g_BdecC[Gsz];
__device__ double g_loss;
// init barrier (full grid): monotonic counters
__device__ unsigned g_grpcnt[8];
__device__ unsigned g_rootcnt;
__device__ volatile unsigned g_gen;
// per-row-group barriers (64 CTAs each): 4 subgroups x 16 CTAs
__device__ unsigned g_grpcnt2[2][4];
__device__ unsigned g_rootcnt2[2];
__device__ volatile unsigned g_gen2[2];

// ---------------- full-grid barrier (init only) ----------------
__device__ __forceinline__ void grid_sync_all() {
    __syncthreads();
    if (threadIdx.x == 0) {
        unsigned g = g_gen;
        __threadfence();
        unsigned a = atomicAdd(&g_grpcnt[blockIdx.x >> 4], 1u);
        if ((a & 15u) == 15u) {
            unsigned r = atomicAdd(&g_rootcnt, 1u);
            if ((r & 7u) == 7u) { __threadfence(); g_gen = g + 1u; }
        }
        while (g_gen == g) { __nanosleep(20); }
        __threadfence();
    }
    __syncthreads();
}

// ---------------- per-row-group barrier: 64 CTAs (4 x 16 tree) ----------------
__device__ __forceinline__ void grid_sync_rg(int rg, int cg) {
    __syncthreads();
    if (threadIdx.x == 0) {
        unsigned g = g_gen2[rg];
        __threadfence();
        unsigned a = atomicAdd(&g_grpcnt2[rg][cg >> 4], 1u);
        if ((a & 15u) == 15u) {
            unsigned r = atomicAdd(&g_rootcnt2[rg], 1u);
            if ((r & 3u) == 3u) { __threadfence(); g_gen2[rg] = g + 1u; }
        }
        while (g_gen2[rg] == g) { __nanosleep(20); }
        __threadfence();
    }
    __syncthreads();
}

__device__ __forceinline__ float sigf(float x) { return 1.f / (1.f + __expf(-x)); }

#define NBAR(id) asm volatile("bar.sync %0, 128;" :: "r"(id) : "memory")
#define WAITG0() asm volatile("cp.async.wait_group 0;\n" ::: "memory")
#define WAITG1() asm volatile("cp.async.wait_group 1;\n" ::: "memory")

// ---------------- 64-k chunk loader: 64 rows x 64 halfs by ONE k-group ----------------
// MODE 0: encoder (chunks 0,1 = x_t halves; chunks 2.. = h), MODE 1: decoder (all h)
template<int MODE>
__device__ __forceinline__ void loadK(__half* As, int c, int rowbase, int t,
                                      int tl, const __half* __restrict__ hin) {
#pragma unroll
    for (int i = 0; i < 4; i++) {
        int idx = tl + i * 128;          // 0..511 -> 512 x 16B segments
        int r   = idx >> 3;
        int kq  = (idx & 7) * 8;
        const __half* gp;
        if (MODE == 0 && c < 2) {
            gp = g_Xh + ((size_t)(rowbase + r) * Ssz + t) * Dsz + c * 64 + kq;
        } else {
            int kc = (MODE == 0) ? (c - 2) * 64 : c * 64;
            gp = hin + (size_t)(rowbase + r) * Hsz + kc + kq;
        }
        unsigned sa = (unsigned)__cvta_generic_to_shared(As + r * ASTR + kq);
        asm volatile("cp.async.cg.shared.global [%0], [%1], 16;\n" :: "r"(sa), "l"(gp));
    }
    asm volatile("cp.async.commit_group;\n" ::: "memory");
}

// ---------------- k-split GEMM: 4 k-groups x (2x2 of 32x32 tiles) ----------------
// kg = wid>>2 owns chunks c == kg (mod 4); groups pipeline independently with
// named barriers (id kg+1, 128 threads). Partials reduced via smem by kg 0.
template<int NC, int MODE>
__device__ __forceinline__ void gemm_step(const __half* __restrict__ Ws,
                                          char* smem_raw, int rowbase, int t,
                                          const __half* __restrict__ hin) {
    const int tid  = threadIdx.x;
    const int wid  = tid >> 5, lane = tid & 31;
    const int kg   = wid >> 2, pos = wid & 3;
    const int pr   = pos >> 1, pc = pos & 1;
    const int quad = lane >> 2, tq = lane & 3;
    const int tl   = tid & 127;
    const int barid = kg + 1;
    const int cnt = (NC + 3 - kg) >> 2;

    const int aRow = lane & 15;
    const int aK   = ((lane >> 4) & 1) * 8;
    const int bN   = ((lane >> 4) * 8) + (lane & 7);
    const int bK   = ((lane >> 3) & 1) * 8;

    __half* b0h = (__half*)(smem_raw + AOFF + (2 * kg) * ABUF);
    __half* b1h = (__half*)(smem_raw + AOFF + (2 * kg + 1) * ABUF);
    float*  Red = (float*)(smem_raw + REDOFF);
    float*  Osm = (float*)(smem_raw + OSMOFF);

    float acc[2][4][4];
#pragma unroll
    for (int mi = 0; mi < 2; mi++)
#pragma unroll
        for (int ni = 0; ni < 4; ni++)
#pragma unroll
            for (int q = 0; q < 4; q++) acc[mi][ni][q] = 0.f;

    // prologue: first two chunks of this k-group
    loadK<MODE>(b0h, kg, rowbase, t, tl, hin);
    loadK<MODE>(b1h, kg + 4, rowbase, t, tl, hin);
    WAITG1();
    NBAR(barid);

    for (int jj = 0; jj < cnt; jj++) {
        const int c = kg + 4 * jj;
        const __half* cur = (jj & 1) ? b1h : b0h;
        const __half* bcol = Ws + (size_t)(pc * 32 + bN) * WSTR + c * 64 + bK;
        const __half* arow = cur + (pr * 32 + aRow) * ASTR + aK;
#pragma unroll
        for (int kk = 0; kk < 4; kk++) {
            unsigned bf[2][4];
#pragma unroll
            for (int n2 = 0; n2 < 2; n2++) {
                unsigned ba = (unsigned)__cvta_generic_to_shared(
                                  bcol + n2 * 16 * WSTR + kk * 16);
                asm volatile(
                    "ldmatrix.sync.aligned.m8n8.x4.shared.b16 {%0,%1,%2,%3}, [%4];\n"
                    : "=r"(bf[n2][0]), "=r"(bf[n2][1]), "=r"(bf[n2][2]), "=r"(bf[n2][3])
                    : "r"(ba));
            }
#pragma unroll
            for (int mi = 0; mi < 2; mi++) {
                unsigned a0, a1, a2, a3;
                unsigned aa = (unsigned)__cvta_generic_to_shared(
                                  arow + mi * 16 * ASTR + kk * 16);
                asm volatile(
                    "ldmatrix.sync.aligned.m8n8.x4.shared.b16 {%0,%1,%2,%3}, [%4];\n"
                    : "=r"(a0), "=r"(a1), "=r"(a2), "=r"(a3) : "r"(aa));
#pragma unroll
                for (int n2 = 0; n2 < 2; n2++) {
                    asm volatile(
                        "mma.sync.aligned.m16n8k16.row.col.f32.f16.f16.f32 "
                        "{%0,%1,%2,%3}, {%4,%5,%6,%7}, {%8,%9}, {%0,%1,%2,%3};\n"
                        : "+f"(acc[mi][n2*2][0]), "+f"(acc[mi][n2*2][1]),
                          "+f"(acc[mi][n2*2][2]), "+f"(acc[mi][n2*2][3])
                        : "r"(a0), "r"(a1), "r"(a2), "r"(a3),
                          "r"(bf[n2][0]), "r"(bf[n2][1]));
                    asm volatile(
                        "mma.sync.aligned.m16n8k16.row.col.f32.f16.f16.f32 "
                        "{%0,%1,%2,%3}, {%4,%5,%6,%7}, {%8,%9}, {%0,%1,%2,%3};\n"
                        : "+f"(acc[mi][n2*2+1][0]), "+f"(acc[mi][n2*2+1][1]),
                          "+f"(acc[mi][n2*2+1][2]), "+f"(acc[mi][n2*2+1][3])
                        : "r"(a0), "r"(a1), "r"(a2), "r"(a3),
                          "r"(bf[n2][2]), "r"(bf[n2][3]));
                }
            }
        }
        NBAR(barid);   // all kg warps done with this buffer
        if (jj + 2 < cnt) {
            loadK<MODE>((jj & 1) ? b1h : b0h, kg + 4 * (jj + 2), rowbase, t, tl, hin);
            WAITG1();  // previous chunk's group landed (this thread)
            NBAR(barid);   // publish to kg's other warps
        } else if (jj + 1 < cnt) {
            WAITG0();
            NBAR(barid);
        }
    }
    __syncthreads();   // all k-groups done; buffers free (Red/Osm overlay them)

    // ---- reduction: kg 1..3 store partials, kg 0 accumulates + writes Osm ----
    if (kg != 0) {
        float* red = Red + ((kg - 1) * 4 + pos) * (32 * RSTR);
#pragma unroll
        for (int mi = 0; mi < 2; mi++)
#pragma unroll
            for (int ni = 0; ni < 4; ni++) {
                int rl = mi * 16 + quad, cl = ni * 8 + tq * 2;
                *(float2*)&red[rl * RSTR + cl]       = make_float2(acc[mi][ni][0], acc[mi][ni][1]);
                *(float2*)&red[(rl + 8) * RSTR + cl] = make_float2(acc[mi][ni][2], acc[mi][ni][3]);
            }
    }
    __syncthreads();
    if (kg == 0) {
#pragma unroll
        for (int g = 0; g < 3; g++) {
            const float* red = Red + (g * 4 + pos) * (32 * RSTR);
#pragma unroll
            for (int mi = 0; mi < 2; mi++)
#pragma unroll
                for (int ni = 0; ni < 4; ni++) {
                    int rl = mi * 16 + quad, cl = ni * 8 + tq * 2;
                    float2 p0 = *(const float2*)&red[rl * RSTR + cl];
                    float2 p1 = *(const float2*)&red[(rl + 8) * RSTR + cl];
                    acc[mi][ni][0] += p0.x; acc[mi][ni][1] += p0.y;
                    acc[mi][ni][2] += p1.x; acc[mi][ni][3] += p1.y;
                }
        }
#pragma unroll
        for (int mi = 0; mi < 2; mi++)
#pragma unroll
            for (int ni = 0; ni < 4; ni++) {
                int row = pr * 32 + mi * 16 + quad;
                int col = pc * 32 + ni * 8 + tq * 2;
                *(float2*)&Osm[row * OSTR + col]       = make_float2(acc[mi][ni][0], acc[mi][ni][1]);
                *(float2*)&Osm[(row + 8) * OSTR + col] = make_float2(acc[mi][ni][2], acc[mi][ni][3]);
            }
    }
    __syncthreads();   // Osm complete before pointwise
}

// ---------------- LSTM pointwise: 512 threads, 1 half2 each ----------------
__device__ __forceinline__ void pointwise(const float* __restrict__ Osm,
                                          const float* __restrict__ Bsm,
                                          float* __restrict__ Csm,
                                          int rg, int cg, int t,
                                          float* __restrict__ out,
                                          __half* __restrict__ hout,
                                          int writeEnc, int writeDec) {
    const int tid = threadIdx.x;
    int row = tid >> 3;            // 0..63
    int jc  = (tid & 7) * 2;       // 0,2..14
    int hc  = cg * 16 + jc;
    int bg  = rg * 64 + row;
    float2 i2 = *(const float2*)&Osm[row * OSTR + jc];
    float2 f2 = *(const float2*)&Osm[row * OSTR + 16 + jc];
    float2 g2 = *(const float2*)&Osm[row * OSTR + 32 + jc];
    float2 o2 = *(const float2*)&Osm[row * OSTR + 48 + jc];
    float iv0 = sigf(i2.x + Bsm[jc]),       iv1 = sigf(i2.y + Bsm[jc + 1]);
    float fv0 = sigf(f2.x + Bsm[16 + jc]),  fv1 = sigf(f2.y + Bsm[17 + jc]);
    float gv0 = tanhf(g2.x + Bsm[32 + jc]), gv1 = tanhf(g2.y + Bsm[33 + jc]);
    float ov0 = sigf(o2.x + Bsm[48 + jc]),  ov1 = sigf(o2.y + Bsm[49 + jc]);
    float2 cold = *(const float2*)&Csm[row * 16 + jc];
    float c0 = fv0 * cold.x + iv0 * gv0;
    float c1 = fv1 * cold.y + iv1 * gv1;
    *(float2*)&Csm[row * 16 + jc] = make_float2(c0, c1);
    float h0 = ov0 * tanhf(c0), h1 = ov1 * tanhf(c1);
    size_t off = (size_t)bg * Hsz + hc;
    *(__half2*)&hout[off] = __floats2half2_rn(h0, h1);
    if (writeEnc)
        *(float2*)&out[(size_t)ENCOFF + ((size_t)bg * Ssz + t) * Hsz + hc] = make_float2(h0, h1);
    if (writeDec)
        *(__half2*)&g_Hdec[((size_t)bg * Ssz + t) * Hsz + hc] = __floats2half2_rn(h0, h1);
}

// ============================== persistent LSTM kernel ==============================
__global__ void __launch_bounds__(NT, 1)
lstm_ae_kernel(const float* __restrict__ x,
               const float* __restrict__ eWih, const float* __restrict__ eWhh,
               const float* __restrict__ ebih, const float* __restrict__ ebhh,
               const float* __restrict__ dWih, const float* __restrict__ dWhh,
               const float* __restrict__ dbih, const float* __restrict__ dbhh,
               const float* __restrict__ oW,   const float* __restrict__ ob,
               float* __restrict__ out, int out_size) {
    extern __shared__ __align__(16) char smem_raw[];
    __half* Ws  = (__half*)smem_raw;
    float*  Osm = (float*)(smem_raw + OSMOFF);
    float*  Csm = (float*)(smem_raw + CSOFF);
    float*  Bsm = (float*)(smem_raw + BSOFF);

    const int bid = blockIdx.x, tid = threadIdx.x;
    const int rg = bid >> 6;      // batch-row group (0..1)
    const int cg = bid & 63;      // h-col group (0..63)
    const int hasEnc = (out_size >= RECONSZ + ENCSZ) ? 1 : 0;

    // ================= init =================
    if (bid == 0 && tid == 0) g_loss = 0.0;

    {   // x -> fp16
        const float4* xv = (const float4*)x;
        __half2* hp = (__half2*)g_Xh;
        size_t n4 = (size_t)Bsz * Ssz * Dsz / 4;
        for (size_t i = (size_t)bid * NT + tid; i < n4; i += (size_t)NB * NT) {
            float4 v = xv[i];
            hp[i * 2]     = __floats2half2_rn(v.x, v.y);
            hp[i * 2 + 1] = __floats2half2_rn(v.z, v.w);
        }
    }
    for (int i = bid * NT + tid; i < Bsz * Hsz; i += NB * NT)
        g_Hbuf[0][i] = __float2half(0.f);
    for (int i = bid * NT + tid; i < Dsz * Hsz; i += NB * NT)
        g_oWh[i] = __float2half(oW[i]);
    for (int R = bid * NT + tid; R < Gsz; R += NB * NT) {
        g_Benc[R] = ebih[R] + ebhh[R];
        float b0 = dbih[R] + dbhh[R];
        g_Bdec0[R] = b0;
        float s = 0.f;
        const float* wr_ = dWih + (size_t)R * Hsz;
        for (int d = 0; d < 128; d++) s += wr_[d] * ob[d];
        g_BdecC[R] = b0 + s;
    }
    {   // Wcomb = dec_Whh + dec_Wih[:,:128] @ out_W   (this block: rows bid*32..+32)
        int R0 = bid * 32;
        int qr = tid >> 7;                  // 0..3 -> 8-row slices
        int k0 = (tid & 127) * 8;
        for (int r = qr * 8; r < qr * 8 + 8; r++) {
            int R = R0 + r;
            const float* wr_ = dWih + (size_t)R * Hsz;
            float a8[8];
#pragma unroll
            for (int q = 0; q < 8; q++) a8[q] = dWhh[(size_t)R * Hsz + k0 + q];
            for (int d = 0; d < 128; d++) {
                float w = wr_[d];
                const float* owp = oW + (size_t)d * Hsz + k0;
#pragma unroll
                for (int q = 0; q < 8; q++) a8[q] += w * owp[q];
            }
#pragma unroll
            for (int q = 0; q < 8; q++)
                g_Wcomb[(size_t)R * Hsz + k0 + q] = __float2half(a8[q]);
        }
    }
    grid_sync_all();

    int par = 0;   // h read-buffer parity

    // ================= encoder =================
    for (int i = tid; i < 1024; i += NT) Csm[i] = 0.f;
    if (tid < 64) Bsm[tid] = g_Benc[(tid >> 4) * Hsz + cg * 16 + (tid & 15)];
    for (int r = 0; r < 64; r++) {
        int R = (r >> 4) * Hsz + cg * 16 + (r & 15);
        for (int k = tid; k < 1152; k += NT) {
            float v = (k < 128) ? eWih[(size_t)R * Dsz + k] : eWhh[(size_t)R * Hsz + (k - 128)];
            Ws[r * WSTR + k] = __float2half(v);
        }
    }
    __syncthreads();
    for (int t = 0; t < Ssz; t++) {
        gemm_step<NCENC, 0>(Ws, smem_raw, rg * 64, t, g_Hbuf[par]);
        pointwise(Osm, Bsm, Csm, rg, cg, t, out, g_Hbuf[par ^ 1], hasEnc, 0);
        par ^= 1;
        grid_sync_rg(rg, cg);
    }

    // ================= decoder step 0 (input = h_n, weights Wih+Whh) =================
    if (tid < 64) Bsm[tid] = g_Bdec0[(tid >> 4) * Hsz + cg * 16 + (tid & 15)];
    for (int r = 0; r < 64; r++) {
        int R = (r >> 4) * Hsz + cg * 16 + (r & 15);
        for (int k = tid; k < 1024; k += NT)
            Ws[r * WSTR + k] = __float2half(dWih[(size_t)R * Hsz + k] + dWhh[(size_t)R * Hsz + k]);
    }
    __syncthreads();
    gemm_step<NCDEC, 1>(Ws, smem_raw, rg * 64, 0, g_Hbuf[par]);
    pointwise(Osm, Bsm, Csm, rg, cg, 0, out, g_Hbuf[par ^ 1], 0, 1);
    par ^= 1;
    grid_sync_rg(rg, cg);

    // ================= decoder steps 1..511 (folded weights) =================
    if (tid < 64) Bsm[tid] = g_BdecC[(tid >> 4) * Hsz + cg * 16 + (tid & 15)];
    for (int s = tid; s < 64 * 128; s += NT) {     // 8192 x uint4 segments
        int r  = s >> 7;
        int sg = (s & 127) * 8;
        int R  = (r >> 4) * Hsz + cg * 16 + (r & 15);
        *(uint4*)&Ws[r * WSTR + sg] = *(const uint4*)&g_Wcomb[(size_t)R * Hsz + sg];
    }
    __syncthreads();
    for (int t = 1; t < Ssz; t++) {
        gemm_step<NCDEC, 1>(Ws, smem_raw, rg * 64, t, g_Hbuf[par]);
        pointwise(Osm, Bsm, Csm, rg, cg, t, out, g_Hbuf[par ^ 1], 0, 1);
        par ^= 1;
        grid_sync_rg(rg, cg);
    }
}

// ============== recon = Hdec @ out_W^T + out_b  (+ fused loss) ==============
#define RASTR 72
__global__ void __launch_bounds__(256)
recon_kernel(const float* __restrict__ x, const float* __restrict__ ob,
             float* __restrict__ out, int out_size) {
    __shared__ __align__(16) __half Asm[64 * RASTR];
    __shared__ __align__(16) __half Wsm[128 * RASTR];

    const int tid  = threadIdx.x;
    const int wid  = tid >> 5, lane = tid & 31;
    const int wr   = wid >> 2, wc   = wid & 3;     // 2x4 warps -> 64x128 tile
    const int quad = lane >> 2, tq  = lane & 3;
    const int rowbase = blockIdx.x * 64;           // 1024 blocks
    const int doRecon = (out_size >= RECONSZ) ? 1 : 0;

    float acc[2][4][4];
#pragma unroll
    for (int mi = 0; mi < 2; mi++)
#pragma unroll
        for (int ni = 0; ni < 4; ni++)
#pragma unroll
            for (int q = 0; q < 4; q++) acc[mi][ni][q] = 0.f;

    for (int c = 0; c < 16; c++) {
        const int kabs = c * 64;
#pragma unroll
        for (int j = 0; j < 2; j++) {   // A: 64 rows x 64 halfs
            int idx = tid + j * 256;
            int r = idx >> 3, kq = (idx & 7) * 8;
            *(uint4*)&Asm[r * RASTR + kq] =
                *(const uint4*)(g_Hdec + (size_t)(rowbase + r) * Hsz + kabs + kq);
        }
#pragma unroll
        for (int j = 0; j < 4; j++) {   // W: 128 rows x 64 halfs
            int idx = tid + j * 256;
            int n = idx >> 3, kq = (idx & 7) * 8;
            *(uint4*)&Wsm[n * RASTR + kq] =
                *(const uint4*)(g_oWh + (size_t)n * Hsz + kabs + kq);
        }
        __syncthreads();
#pragma unroll
        for (int kk = 0; kk < 4; kk++) {
            unsigned bfr[4][2];
#pragma unroll
            for (int ni = 0; ni < 4; ni++) {
                const __half* bp = Wsm + (wc * 32 + ni * 8 + quad) * RASTR + kk * 16 + tq * 2;
                bfr[ni][0] = *(const unsigned*)bp;
                bfr[ni][1] = *(const unsigned*)(bp + 8);
            }
#pragma unroll
            for (int mi = 0; mi < 2; mi++) {
                const __half* ap = Asm + (wr * 32 + mi * 16 + quad) * RASTR + kk * 16 + tq * 2;
                unsigned a0 = *(const unsigned*)ap;
                unsigned a1 = *(const unsigned*)(ap + 8 * RASTR);
                unsigned a2 = *(const unsigned*)(ap + 8);
                unsigned a3 = *(const unsigned*)(ap + 8 * RASTR + 8);
#pragma unroll
                for (int ni = 0; ni < 4; ni++)
                    asm volatile(
                        "mma.sync.aligned.m16n8k16.row.col.f32.f16.f16.f32 "
                        "{%0,%1,%2,%3}, {%4,%5,%6,%7}, {%8,%9}, {%0,%1,%2,%3};\n"
                        : "+f"(acc[mi][ni][0]), "+f"(acc[mi][ni][1]),
                          "+f"(acc[mi][ni][2]), "+f"(acc[mi][ni][3])
                        : "r"(a0), "r"(a1), "r"(a2), "r"(a3),
                          "r"(bfr[ni][0]), "r"(bfr[ni][1]));
            }
        }
        __syncthreads();
    }

    // epilogue: add bias, write recon, accumulate loss
    float lsum = 0.f;
#pragma unroll
    for (int mi = 0; mi < 2; mi++)
#pragma unroll
        for (int ni = 0; ni < 4; ni++) {
            int row = rowbase + wr * 32 + mi * 16 + quad;
            int col = wc * 32 + ni * 8 + tq * 2;
            float b0 = ob[col], b1 = ob[col + 1];
#pragma unroll
            for (int half_ = 0; half_ < 2; half_++) {
                int rr = row + half_ * 8;
                float v0 = acc[mi][ni][half_ * 2]     + b0;
                float v1 = acc[mi][ni][half_ * 2 + 1] + b1;
                size_t o = (size_t)rr * Dsz + col;
                float d0 = v0 - x[o], d1 = v1 - x[o + 1];
                lsum += d0 * d0 + d1 * d1;
                if (doRecon) { out[o] = v0; out[o + 1] = v1; }
            }
        }
#pragma unroll
    for (int off = 16; off > 0; off >>= 1)
        lsum += __shfl_xor_sync(0xffffffffu, lsum, off);
    if (lane == 0) atomicAdd(&g_loss, (double)lsum);
}

__global__ void loss_finish(float* __restrict__ out, int out_size) {
    if (out_size >= TOTSZ) out[RECONSZ + ENCSZ] = (float)(g_loss * (1.0 / 128.0));
}

// ============================== launch ==============================
extern "C" void kernel_launch(void* const* d_in, const int* in_sizes, int n_in,
                              void* d_out, int out_size) {
    const float* x     = (const float*)d_in[0];
    const float* eWih  = (const float*)d_in[1];
    const float* eWhh  = (const float*)d_in[2];
    const float* ebih  = (const float*)d_in[3];
    const float* ebhh  = (const float*)d_in[4];
    const float* dWih  = (const float*)d_in[5];
    const float* dWhh  = (const float*)d_in[6];
    const float* dbih  = (const float*)d_in[7];
    const float* dbhh  = (const float*)d_in[8];
    const float* oW    = (const float*)d_in[9];
    const float* ob    = (const float*)d_in[10];
    float* out = (float*)d_out;

    cudaFuncSetAttribute(lstm_ae_kernel,
                         cudaFuncAttributeMaxDynamicSharedMemorySize, SMEM_BYTES);

    lstm_ae_kernel<<<NB, NT, SMEM_BYTES>>>(x, eWih, eWhh, ebih, ebhh,
                                           dWih, dWhh, dbih, dbhh, oW, ob,
                                           out, out_size);
    recon_kernel<<<(Bsz * Ssz) / 64, 256>>>(x, ob, out, out_size);
    loss_finish<<<1, 1>>>(out, out_size);
}